// round 1
// baseline (speedup 1.0000x reference)
#include <cuda_runtime.h>
#include <math.h>

#define BB 32
#define SS 4096
#define DD 512
#define BM 64
#define BN 64
#define BK 32

// scratch (no allocation allowed)
__device__ float g_qadd[BB * DD];        // q@W1 + b1 + b2
__device__ float g_scores[BB * SS];      // logits
__device__ float g_partial[BB * 8 * DD]; // context partials

// ---------------------------------------------------------------------------
// Kernel 1: q_proj[b][n] = sum_k query[b][k] * W1[k][n] + b1[n] + b2[n]
// ---------------------------------------------------------------------------
__global__ void __launch_bounds__(256) qproj_kernel(
    const float* __restrict__ query, const float* __restrict__ W1,
    const float* __restrict__ b1, const float* __restrict__ b2) {
  int b = blockIdx.x;
  __shared__ float qs[DD];
  for (int i = threadIdx.x; i < DD; i += 256) qs[i] = query[b * DD + i];
  __syncthreads();
  for (int n = threadIdx.x; n < DD; n += 256) {
    float acc = 0.f;
#pragma unroll 8
    for (int k = 0; k < DD; k++) acc = fmaf(qs[k], W1[k * DD + n], acc);
    g_qadd[b * DD + n] = acc + b1[n] + b2[n];
  }
}

// ---------------------------------------------------------------------------
// Kernel 2: fused scores. Per block: 64 rows of values resident in SMEM,
// W2 streamed as 32x64 double-buffered tiles with register prefetch.
// Epilogue fuses tanh(vproj + qadd) . V  with a 16-lane shfl reduction.
// ---------------------------------------------------------------------------
__global__ void __launch_bounds__(256) score_kernel(
    const float* __restrict__ values, const float* __restrict__ W2,
    const float* __restrict__ Vv, const float* __restrict__ bv) {
  extern __shared__ float smem[];
  float* Vs = smem;                 // BM * DD        (131072 B)
  float* Wst = Vs + BM * DD;        // 2 * BK * BN    (16384 B)
  float* qsh = Wst + 2 * BK * BN;   // DD
  float* vsh = qsh + DD;            // DD

  const int tid = threadIdx.x;
  const int m0 = blockIdx.x * BM;   // global row base (never crosses b: S%64==0)
  const int b = m0 / SS;
  const int tr = tid >> 4;          // 0..15 -> 4 rows each
  const int tc = tid & 15;          // 0..15 -> 4 cols each

  // Load values tile (contiguous 64*512 floats), qadd row, V vector.
  {
    const float4* src = (const float4*)(values + (size_t)m0 * DD);
    float4* dst = (float4*)Vs;
#pragma unroll
    for (int i = 0; i < (BM * DD / 4) / 256; i++)
      dst[tid + i * 256] = src[tid + i * 256];
    for (int i = tid; i < DD; i += 256) {
      qsh[i] = g_qadd[b * DD + i];
      vsh[i] = Vv[i];
    }
  }
  __syncthreads();

  float srow[4] = {0.f, 0.f, 0.f, 0.f};

  // W2 tile load mapping: stage has BK*BN = 512 float4; thread owns l=tid, tid+256
  const int kk0 = tid >> 4, c40 = tid & 15;
  const int kk1 = (tid + 256) >> 4, c41 = (tid + 256) & 15;

  for (int nc = 0; nc < DD / BN; nc++) {
    const float4* Wg = (const float4*)(W2 + nc * BN);  // row stride 128 float4
    float acc[4][4] = {{0.f, 0.f, 0.f, 0.f}, {0.f, 0.f, 0.f, 0.f},
                       {0.f, 0.f, 0.f, 0.f}, {0.f, 0.f, 0.f, 0.f}};

    // stage 0
    ((float4*)Wst)[tid] = Wg[kk0 * 128 + c40];
    ((float4*)Wst)[tid + 256] = Wg[kk1 * 128 + c41];
    __syncthreads();

    for (int kt = 0; kt < DD / BK; kt++) {
      float4 pf0, pf1;
      if (kt < DD / BK - 1) {
        pf0 = Wg[((kt + 1) * BK + kk0) * 128 + c40];
        pf1 = Wg[((kt + 1) * BK + kk1) * 128 + c41];
      }
      const float* Wc = Wst + (kt & 1) * BK * BN;
      const float* Vp = Vs + (tr * 4) * DD + kt * BK;
#pragma unroll
      for (int kk = 0; kk < BK; kk++) {
        float4 wv = ((const float4*)(Wc + kk * BN))[tc];
        float a0 = Vp[0 * DD + kk];
        float a1 = Vp[1 * DD + kk];
        float a2 = Vp[2 * DD + kk];
        float a3 = Vp[3 * DD + kk];
        acc[0][0] = fmaf(a0, wv.x, acc[0][0]);
        acc[0][1] = fmaf(a0, wv.y, acc[0][1]);
        acc[0][2] = fmaf(a0, wv.z, acc[0][2]);
        acc[0][3] = fmaf(a0, wv.w, acc[0][3]);
        acc[1][0] = fmaf(a1, wv.x, acc[1][0]);
        acc[1][1] = fmaf(a1, wv.y, acc[1][1]);
        acc[1][2] = fmaf(a1, wv.z, acc[1][2]);
        acc[1][3] = fmaf(a1, wv.w, acc[1][3]);
        acc[2][0] = fmaf(a2, wv.x, acc[2][0]);
        acc[2][1] = fmaf(a2, wv.y, acc[2][1]);
        acc[2][2] = fmaf(a2, wv.z, acc[2][2]);
        acc[2][3] = fmaf(a2, wv.w, acc[2][3]);
        acc[3][0] = fmaf(a3, wv.x, acc[3][0]);
        acc[3][1] = fmaf(a3, wv.y, acc[3][1]);
        acc[3][2] = fmaf(a3, wv.z, acc[3][2]);
        acc[3][3] = fmaf(a3, wv.w, acc[3][3]);
      }
      if (kt < DD / BK - 1) {
        float4* Wn = (float4*)(Wst + ((kt + 1) & 1) * BK * BN);
        Wn[tid] = pf0;
        Wn[tid + 256] = pf1;
        __syncthreads();
      }
    }

    // epilogue: tanh + dot with V over this 64-col chunk
#pragma unroll
    for (int i = 0; i < 4; i++) {
      float ssum = 0.f;
#pragma unroll
      for (int j = 0; j < 4; j++) {
        int c = nc * BN + tc * 4 + j;
        float h = tanhf(acc[i][j] + qsh[c]);
        ssum = fmaf(h, vsh[c], ssum);
      }
      ssum += __shfl_xor_sync(0xffffffffu, ssum, 8);
      ssum += __shfl_xor_sync(0xffffffffu, ssum, 4);
      ssum += __shfl_xor_sync(0xffffffffu, ssum, 2);
      ssum += __shfl_xor_sync(0xffffffffu, ssum, 1);
      srow[i] += ssum;
    }
    __syncthreads();  // stage0 of next chunk overwrites Wst
  }

  if (tc == 0) {
    float bvv = bv[0];
#pragma unroll
    for (int i = 0; i < 4; i++) g_scores[m0 + tr * 4 + i] = srow[i] + bvv;
  }
}

// ---------------------------------------------------------------------------
// Kernel 3: softmax over S per batch, writes attn into d_out[B*D ..]
// ---------------------------------------------------------------------------
__global__ void __launch_bounds__(256) softmax_kernel(float* __restrict__ out) {
  int b = blockIdx.x;
  const float* sc = g_scores + b * SS;
  float* attn = out + BB * DD + (size_t)b * SS;
  __shared__ float redm[8];
  __shared__ float reds[8];
  __shared__ float bm, bs;
  int tid = threadIdx.x, lane = tid & 31, w = tid >> 5;

  float m = -1e30f;
  for (int i = tid; i < SS; i += 256) m = fmaxf(m, sc[i]);
#pragma unroll
  for (int o = 16; o; o >>= 1) m = fmaxf(m, __shfl_xor_sync(0xffffffffu, m, o));
  if (lane == 0) redm[w] = m;
  __syncthreads();
  if (tid == 0) {
    float v = redm[0];
#pragma unroll
    for (int i = 1; i < 8; i++) v = fmaxf(v, redm[i]);
    bm = v;
  }
  __syncthreads();
  m = bm;

  float sum = 0.f;
  for (int i = tid; i < SS; i += 256) sum += expf(sc[i] - m);
#pragma unroll
  for (int o = 16; o; o >>= 1) sum += __shfl_xor_sync(0xffffffffu, sum, o);
  if (lane == 0) reds[w] = sum;
  __syncthreads();
  if (tid == 0) {
    float v = 0.f;
#pragma unroll
    for (int i = 0; i < 8; i++) v += reds[i];
    bs = v;
  }
  __syncthreads();
  float inv = 1.0f / bs;
  for (int i = tid; i < SS; i += 256) attn[i] = expf(sc[i] - m) * inv;
}

// ---------------------------------------------------------------------------
// Kernel 4: context partials. grid(dchunk=4, schunk=8, b=32), 128 threads.
// Deterministic (no float atomics): each block owns a distinct partial slot.
// ---------------------------------------------------------------------------
__global__ void __launch_bounds__(128) ctx_partial_kernel(
    const float* __restrict__ values, const float* __restrict__ out) {
  int d = blockIdx.x * 128 + threadIdx.x;
  int scnk = blockIdx.y;
  int b = blockIdx.z;
  const float* attn = out + BB * DD + (size_t)b * SS + scnk * (SS / 8);
  const float* vb = values + ((size_t)b * SS + (size_t)scnk * (SS / 8)) * DD + d;
  float acc = 0.f;
  for (int s = 0; s < SS / 8; s += 8) {
#pragma unroll
    for (int u = 0; u < 8; u++)
      acc = fmaf(attn[s + u], vb[(size_t)(s + u) * DD], acc);
  }
  g_partial[((b * 8) + scnk) * DD + d] = acc;
}

// Kernel 5: final deterministic reduce of partials -> context in d_out[0..B*D)
__global__ void __launch_bounds__(256) ctx_reduce_kernel(float* __restrict__ out) {
  int idx = blockIdx.x * 256 + threadIdx.x;  // over B*D = 16384
  if (idx >= BB * DD) return;
  int b = idx >> 9;
  int d = idx & 511;
  float acc = 0.f;
#pragma unroll
  for (int p = 0; p < 8; p++) acc += g_partial[(b * 8 + p) * DD + d];
  out[idx] = acc;
}

// ---------------------------------------------------------------------------
extern "C" void kernel_launch(void* const* d_in, const int* in_sizes, int n_in,
                              void* d_out, int out_size) {
  const float* query = (const float*)d_in[0];
  const float* values = (const float*)d_in[1];
  const float* W1 = (const float*)d_in[2];
  const float* b1 = (const float*)d_in[3];
  const float* W2 = (const float*)d_in[4];
  const float* b2 = (const float*)d_in[5];
  const float* Vv = (const float*)d_in[6];
  const float* bv = (const float*)d_in[7];
  float* out = (float*)d_out;

  const int smem_bytes = (BM * DD + 2 * BK * BN + 2 * DD) * sizeof(float);
  cudaFuncSetAttribute(score_kernel, cudaFuncAttributeMaxDynamicSharedMemorySize,
                       smem_bytes);

  qproj_kernel<<<BB, 256>>>(query, W1, b1, b2);
  score_kernel<<<(BB * SS) / BM, 256, smem_bytes>>>(values, W2, Vv, bv);
  softmax_kernel<<<BB, 256>>>(out);
  ctx_partial_kernel<<<dim3(DD / 128, 8, BB), 128>>>(values, out);
  ctx_reduce_kernel<<<(BB * DD + 255) / 256, 256>>>(out);
}

// round 3
// speedup vs baseline: 2.1885x; 2.1885x over previous
#include <cuda_runtime.h>
#include <cuda_bf16.h>
#include <math.h>
#include <cstdint>

#define BB 32
#define SS 4096
#define DD 512

// ---------------------------------------------------------------------------
// scratch (no allocation allowed)
// ---------------------------------------------------------------------------
__device__ float g_qadd[BB * DD];          // q@W1 + b1 + b2
__device__ float g_scores[BB * SS];        // logits
__device__ float g_partial[BB * 8 * DD];   // context partials
__device__ unsigned short g_w2bf[2 * DD * DD];  // bf16 hi/lo W2, [n][k] k-contiguous

// ---------------------------------------------------------------------------
__device__ __forceinline__ float tanh_fast(float x) {
  float ax = fabsf(x);
  float e = __expf(-2.0f * ax);
  float r = __fdividef(1.0f - e, 1.0f + e);
  return copysignf(r, x);
}

__device__ __forceinline__ void split2(float a, float b, uint32_t& h, uint32_t& l) {
  __nv_bfloat162 hh = __floats2bfloat162_rn(a, b);
  float2 hf = __bfloat1622float2(hh);
  __nv_bfloat162 ll = __floats2bfloat162_rn(a - hf.x, b - hf.y);
  h = *reinterpret_cast<uint32_t*>(&hh);
  l = *reinterpret_cast<uint32_t*>(&ll);
}

__device__ __forceinline__ void mma_bf16(float* c, const uint32_t* a, const uint32_t* b) {
  asm volatile(
      "mma.sync.aligned.m16n8k16.row.col.f32.bf16.bf16.f32 "
      "{%0,%1,%2,%3},{%4,%5,%6,%7},{%8,%9},{%0,%1,%2,%3};"
      : "+f"(c[0]), "+f"(c[1]), "+f"(c[2]), "+f"(c[3])
      : "r"(a[0]), "r"(a[1]), "r"(a[2]), "r"(a[3]), "r"(b[0]), "r"(b[1]));
}

// ---------------------------------------------------------------------------
// Kernel 0: W2 -> bf16 hi/lo, transposed to [n][k] (k contiguous)
// ---------------------------------------------------------------------------
__global__ void __launch_bounds__(256) prep_w2_kernel(const float* __restrict__ W2) {
  int idx = blockIdx.x * 256 + threadIdx.x;  // over [k][n]
  int k = idx >> 9, n = idx & 511;
  float x = W2[idx];
  __nv_bfloat16 h = __float2bfloat16(x);
  float hf = __bfloat162float(h);
  __nv_bfloat16 l = __float2bfloat16(x - hf);
  g_w2bf[n * DD + k] = *reinterpret_cast<unsigned short*>(&h);
  g_w2bf[DD * DD + n * DD + k] = *reinterpret_cast<unsigned short*>(&l);
}

// ---------------------------------------------------------------------------
// Kernel 1: q_proj[b][n] = query[b]@W1 + b1 + b2
// ---------------------------------------------------------------------------
__global__ void __launch_bounds__(256) qproj_kernel(
    const float* __restrict__ query, const float* __restrict__ W1,
    const float* __restrict__ b1, const float* __restrict__ b2) {
  int b = blockIdx.x;
  __shared__ float qs[DD];
  for (int i = threadIdx.x; i < DD; i += 256) qs[i] = query[b * DD + i];
  __syncthreads();
  for (int n = threadIdx.x; n < DD; n += 256) {
    float acc = 0.f;
#pragma unroll 8
    for (int k = 0; k < DD; k++) acc = fmaf(qs[k], W1[k * DD + n], acc);
    g_qadd[b * DD + n] = acc + b1[n] + b2[n];
  }
}

// ---------------------------------------------------------------------------
// Kernel 2: score GEMM on tensor cores (mma.sync bf16, 3-term split) + fused
// tanh/V epilogue. Block: 64 rows, A resident bf16 hi/lo, W2 streamed.
// ---------------------------------------------------------------------------
#define A_STRIDE 1040          // (512+8) bf16 * 2 bytes
#define AHI_OFF 0              // 64*1040 = 66560
#define ALO_OFF 66560
#define BST_OFF 133120         // 2 stages * 18432
#define B_STAGE 18432          // hi plane 9216 + lo plane 9216
#define B_RSTRIDE 144          // (64+8) bf16 * 2 bytes
#define Q_OFF 169984
#define V_OFF 172032
#define P_OFF 174080
#define SMEM_TOTAL 175104

__global__ void __launch_bounds__(256, 1) score_mma_kernel(
    const float* __restrict__ values, const float* __restrict__ Vv,
    const float* __restrict__ bv) {
  extern __shared__ char smem[];
  const int tid = threadIdx.x;
  const int wid = tid >> 5, lane = tid & 31;
  const int gid = lane >> 2, tig = lane & 3;
  const int wm = wid & 1, wn = wid >> 1;  // warp tile: rows wm*32+, cols wn*16+
  const int m0 = blockIdx.x * 64;
  const int b = m0 >> 12;

  float* qsh = (float*)(smem + Q_OFF);
  float* vsh = (float*)(smem + V_OFF);
  float* part = (float*)(smem + P_OFF);

  // ---- A fill: 64 rows x 512 k, fp32 -> bf16 hi/lo, padded rows ----
  for (int task = tid; task < 4096; task += 256) {
    int r = task >> 6, g = task & 63;  // g: group of 8 floats
    const float4* p4 = (const float4*)(values + (size_t)(m0 + r) * DD + g * 8);
    float4 x0 = p4[0], x1 = p4[1];
    uint32_t h0, h1, h2, h3, l0, l1, l2, l3;
    split2(x0.x, x0.y, h0, l0);
    split2(x0.z, x0.w, h1, l1);
    split2(x1.x, x1.y, h2, l2);
    split2(x1.z, x1.w, h3, l3);
    uint32_t off = (uint32_t)(r * A_STRIDE + g * 16);
    *(uint4*)(smem + AHI_OFF + off) = make_uint4(h0, h1, h2, h3);
    *(uint4*)(smem + ALO_OFF + off) = make_uint4(l0, l1, l2, l3);
  }
  for (int i = tid; i < DD; i += 256) {
    qsh[i] = g_qadd[b * DD + i];
    vsh[i] = Vv[i];
  }

  // B copy task mapping (512 uint4 per plane; thread owns t=tid, tid+256)
  const int bn0 = tid >> 3, bk0 = tid & 7;
  const int bn1 = (tid + 256) >> 3, bk1 = (tid + 256) & 7;

  // A fragment base pointers (per thread)
  const char* aHbase = smem + AHI_OFF + (wm * 32 + gid) * A_STRIDE + tig * 4;
  const char* aLbase = smem + ALO_OFF + (wm * 32 + gid) * A_STRIDE + tig * 4;

  float rowsum[4] = {0.f, 0.f, 0.f, 0.f};

  for (int nc = 0; nc < 8; ++nc) {
    float acc[2][2][4];
#pragma unroll
    for (int mi = 0; mi < 2; mi++)
#pragma unroll
      for (int ni = 0; ni < 2; ni++)
#pragma unroll
        for (int j = 0; j < 4; j++) acc[mi][ni][j] = 0.f;

    const unsigned short* Bg = g_w2bf + (size_t)(nc * 64) * DD;

    // stage 0 load
    {
      uint4 p0 = *(const uint4*)(Bg + bn0 * DD + bk0 * 8);
      uint4 p1 = *(const uint4*)(Bg + bn1 * DD + bk1 * 8);
      uint4 p2 = *(const uint4*)(Bg + DD * DD + bn0 * DD + bk0 * 8);
      uint4 p3 = *(const uint4*)(Bg + DD * DD + bn1 * DD + bk1 * 8);
      *(uint4*)(smem + BST_OFF + bn0 * B_RSTRIDE + bk0 * 16) = p0;
      *(uint4*)(smem + BST_OFF + bn1 * B_RSTRIDE + bk1 * 16) = p1;
      *(uint4*)(smem + BST_OFF + 9216 + bn0 * B_RSTRIDE + bk0 * 16) = p2;
      *(uint4*)(smem + BST_OFF + 9216 + bn1 * B_RSTRIDE + bk1 * 16) = p3;
    }
    __syncthreads();

    for (int kt = 0; kt < 8; ++kt) {
      uint4 p0, p1, p2, p3;
      if (kt < 7) {
        const unsigned short* src = Bg + (kt + 1) * 64;
        p0 = *(const uint4*)(src + bn0 * DD + bk0 * 8);
        p1 = *(const uint4*)(src + bn1 * DD + bk1 * 8);
        p2 = *(const uint4*)(src + DD * DD + bn0 * DD + bk0 * 8);
        p3 = *(const uint4*)(src + DD * DD + bn1 * DD + bk1 * 8);
      }
      const char* Bst = smem + BST_OFF + (kt & 1) * B_STAGE;
      const char* bHbase = Bst + (wn * 16 + gid) * B_RSTRIDE + tig * 4;
      const char* bLbase = bHbase + 9216;
#pragma unroll
      for (int k16 = 0; k16 < 4; ++k16) {
        int kg = kt * 64 + k16 * 16;  // global k for A
        int kl = k16 * 16;            // stage-local k for B
        uint32_t aH[2][4], aL[2][4], bH[2][2], bL[2][2];
#pragma unroll
        for (int mi = 0; mi < 2; mi++) {
          const char* pH = aHbase + mi * 16 * A_STRIDE + kg * 2;
          const char* pL = aLbase + mi * 16 * A_STRIDE + kg * 2;
          aH[mi][0] = *(const uint32_t*)(pH);
          aH[mi][1] = *(const uint32_t*)(pH + 8 * A_STRIDE);
          aH[mi][2] = *(const uint32_t*)(pH + 16);
          aH[mi][3] = *(const uint32_t*)(pH + 8 * A_STRIDE + 16);
          aL[mi][0] = *(const uint32_t*)(pL);
          aL[mi][1] = *(const uint32_t*)(pL + 8 * A_STRIDE);
          aL[mi][2] = *(const uint32_t*)(pL + 16);
          aL[mi][3] = *(const uint32_t*)(pL + 8 * A_STRIDE + 16);
        }
#pragma unroll
        for (int ni = 0; ni < 2; ni++) {
          const char* pH = bHbase + ni * 8 * B_RSTRIDE + kl * 2;
          const char* pL = bLbase + ni * 8 * B_RSTRIDE + kl * 2;
          bH[ni][0] = *(const uint32_t*)(pH);
          bH[ni][1] = *(const uint32_t*)(pH + 16);
          bL[ni][0] = *(const uint32_t*)(pL);
          bL[ni][1] = *(const uint32_t*)(pL + 16);
        }
#pragma unroll
        for (int mi = 0; mi < 2; mi++)
#pragma unroll
          for (int ni = 0; ni < 2; ni++) {
            mma_bf16(acc[mi][ni], aH[mi], bH[ni]);
            mma_bf16(acc[mi][ni], aH[mi], bL[ni]);
            mma_bf16(acc[mi][ni], aL[mi], bH[ni]);
          }
      }
      if (kt < 7) {
        char* dst = smem + BST_OFF + ((kt + 1) & 1) * B_STAGE;
        *(uint4*)(dst + bn0 * B_RSTRIDE + bk0 * 16) = p0;
        *(uint4*)(dst + bn1 * B_RSTRIDE + bk1 * 16) = p1;
        *(uint4*)(dst + 9216 + bn0 * B_RSTRIDE + bk0 * 16) = p2;
        *(uint4*)(dst + 9216 + bn1 * B_RSTRIDE + bk1 * 16) = p3;
        __syncthreads();
      }
    }

    // epilogue for this 64-col chunk
#pragma unroll
    for (int mi = 0; mi < 2; mi++)
#pragma unroll
      for (int ni = 0; ni < 2; ni++)
#pragma unroll
        for (int ri = 0; ri < 2; ri++)
#pragma unroll
          for (int j = 0; j < 2; j++) {
            int n = nc * 64 + wn * 16 + ni * 8 + tig * 2 + j;
            float h = tanh_fast(acc[mi][ni][ri * 2 + j] + qsh[n]);
            rowsum[mi * 2 + ri] = fmaf(h, vsh[n], rowsum[mi * 2 + ri]);
          }
  }

  // reduce over tig (lanes differing in low 2 bits share a row)
#pragma unroll
  for (int i = 0; i < 4; i++) {
    rowsum[i] += __shfl_xor_sync(0xffffffffu, rowsum[i], 1);
    rowsum[i] += __shfl_xor_sync(0xffffffffu, rowsum[i], 2);
  }
  __syncthreads();  // everyone done reading B stages; reuse part buffer
  if (tig == 0) {
#pragma unroll
    for (int mi = 0; mi < 2; mi++)
#pragma unroll
      for (int ri = 0; ri < 2; ri++) {
        int row = wm * 32 + mi * 16 + ri * 8 + gid;
        part[wn * 64 + row] = rowsum[mi * 2 + ri];
      }
  }
  __syncthreads();
  if (tid < 64) {
    float s = part[tid] + part[64 + tid] + part[128 + tid] + part[192 + tid];
    g_scores[m0 + tid] = s + bv[0];
  }
}

// ---------------------------------------------------------------------------
// Kernel 3: softmax over S per batch, attn -> d_out[B*D ..]
// ---------------------------------------------------------------------------
__global__ void __launch_bounds__(256) softmax_kernel(float* __restrict__ out) {
  int b = blockIdx.x;
  const float* sc = g_scores + b * SS;
  float* attn = out + BB * DD + (size_t)b * SS;
  __shared__ float redm[8];
  __shared__ float reds[8];
  __shared__ float bm, bs;
  int tid = threadIdx.x, lane = tid & 31, w = tid >> 5;

  float m = -1e30f;
  for (int i = tid; i < SS; i += 256) m = fmaxf(m, sc[i]);
#pragma unroll
  for (int o = 16; o; o >>= 1) m = fmaxf(m, __shfl_xor_sync(0xffffffffu, m, o));
  if (lane == 0) redm[w] = m;
  __syncthreads();
  if (tid == 0) {
    float v = redm[0];
#pragma unroll
    for (int i = 1; i < 8; i++) v = fmaxf(v, redm[i]);
    bm = v;
  }
  __syncthreads();
  m = bm;

  float sum = 0.f;
  for (int i = tid; i < SS; i += 256) sum += expf(sc[i] - m);
#pragma unroll
  for (int o = 16; o; o >>= 1) sum += __shfl_xor_sync(0xffffffffu, sum, o);
  if (lane == 0) reds[w] = sum;
  __syncthreads();
  if (tid == 0) {
    float v = 0.f;
#pragma unroll
    for (int i = 0; i < 8; i++) v += reds[i];
    bs = v;
  }
  __syncthreads();
  float inv = 1.0f / bs;
  for (int i = tid; i < SS; i += 256) attn[i] = expf(sc[i] - m) * inv;
}

// ---------------------------------------------------------------------------
// Kernel 4/5: context = sum_s attn * values (deterministic two-stage)
// ---------------------------------------------------------------------------
__global__ void __launch_bounds__(128) ctx_partial_kernel(
    const float* __restrict__ values, const float* __restrict__ out) {
  int d = blockIdx.x * 128 + threadIdx.x;
  int scnk = blockIdx.y;
  int b = blockIdx.z;
  const float* attn = out + BB * DD + (size_t)b * SS + scnk * (SS / 8);
  const float* vb = values + ((size_t)b * SS + (size_t)scnk * (SS / 8)) * DD + d;
  float acc = 0.f;
  for (int s = 0; s < SS / 8; s += 8) {
#pragma unroll
    for (int u = 0; u < 8; u++)
      acc = fmaf(attn[s + u], vb[(size_t)(s + u) * DD], acc);
  }
  g_partial[((b * 8) + scnk) * DD + d] = acc;
}

__global__ void __launch_bounds__(256) ctx_reduce_kernel(float* __restrict__ out) {
  int idx = blockIdx.x * 256 + threadIdx.x;
  if (idx >= BB * DD) return;
  int b = idx >> 9;
  int d = idx & 511;
  float acc = 0.f;
#pragma unroll
  for (int p = 0; p < 8; p++) acc += g_partial[(b * 8 + p) * DD + d];
  out[idx] = acc;
}

// ---------------------------------------------------------------------------
extern "C" void kernel_launch(void* const* d_in, const int* in_sizes, int n_in,
                              void* d_out, int out_size) {
  const float* query = (const float*)d_in[0];
  const float* values = (const float*)d_in[1];
  const float* W1 = (const float*)d_in[2];
  const float* b1 = (const float*)d_in[3];
  const float* W2 = (const float*)d_in[4];
  const float* b2 = (const float*)d_in[5];
  const float* Vv = (const float*)d_in[6];
  const float* bv = (const float*)d_in[7];
  float* out = (float*)d_out;

  cudaFuncSetAttribute(score_mma_kernel,
                       cudaFuncAttributeMaxDynamicSharedMemorySize, SMEM_TOTAL);

  prep_w2_kernel<<<(DD * DD) / 256, 256>>>(W2);
  qproj_kernel<<<BB, 256>>>(query, W1, b1, b2);
  score_mma_kernel<<<(BB * SS) / 64, 256, SMEM_TOTAL>>>(values, Vv, bv);
  softmax_kernel<<<BB, 256>>>(out);
  ctx_partial_kernel<<<dim3(DD / 128, 8, BB), 128>>>(values, out);
  ctx_reduce_kernel<<<(BB * DD + 255) / 256, 256>>>(out);
}

// round 4
// speedup vs baseline: 2.3225x; 1.0612x over previous
#include <cuda_runtime.h>
#include <cuda_bf16.h>
#include <math.h>
#include <cstdint>

#define BB 32
#define SS 4096
#define DD 512

// ---------------------------------------------------------------------------
// scratch (no allocation allowed)
// ---------------------------------------------------------------------------
__device__ float g_qadd[BB * DD];          // q@W1 + b1 + b2
__device__ float g_scores[BB * SS];        // logits
__device__ float g_partial[BB * 8 * DD];   // context partials
__device__ unsigned short g_w2bf[2 * DD * DD];  // bf16 hi/lo W2, [n][k] k-contiguous

// ---------------------------------------------------------------------------
__device__ __forceinline__ float tanh_fast(float x) {
  float ax = fabsf(x);
  float e = __expf(-2.0f * ax);
  float r = __fdividef(1.0f - e, 1.0f + e);
  return copysignf(r, x);
}

__device__ __forceinline__ void split2(float a, float b, uint32_t& h, uint32_t& l) {
  __nv_bfloat162 hh = __floats2bfloat162_rn(a, b);
  float2 hf = __bfloat1622float2(hh);
  __nv_bfloat162 ll = __floats2bfloat162_rn(a - hf.x, b - hf.y);
  h = *reinterpret_cast<uint32_t*>(&hh);
  l = *reinterpret_cast<uint32_t*>(&ll);
}

__device__ __forceinline__ void mma_bf16(float* c, const uint32_t* a, const uint32_t* b) {
  asm volatile(
      "mma.sync.aligned.m16n8k16.row.col.f32.bf16.bf16.f32 "
      "{%0,%1,%2,%3},{%4,%5,%6,%7},{%8,%9},{%0,%1,%2,%3};"
      : "+f"(c[0]), "+f"(c[1]), "+f"(c[2]), "+f"(c[3])
      : "r"(a[0]), "r"(a[1]), "r"(a[2]), "r"(a[3]), "r"(b[0]), "r"(b[1]));
}

__device__ __forceinline__ void ldsm_x4(uint32_t* r, uint32_t addr) {
  asm volatile("ldmatrix.sync.aligned.m8n8.x4.shared.b16 {%0,%1,%2,%3}, [%4];"
               : "=r"(r[0]), "=r"(r[1]), "=r"(r[2]), "=r"(r[3])
               : "r"(addr));
}

__device__ __forceinline__ void cp16(uint32_t dst, const void* src) {
  asm volatile("cp.async.cg.shared.global [%0], [%1], 16;" :: "r"(dst), "l"(src));
}
#define CP_COMMIT() asm volatile("cp.async.commit_group;" ::: "memory")
#define CP_WAIT1() asm volatile("cp.async.wait_group 1;" ::: "memory")
#define CP_WAIT0() asm volatile("cp.async.wait_group 0;" ::: "memory")

__device__ __forceinline__ uint32_t smem_u32(const void* p) {
  uint32_t a;
  asm("{ .reg .u64 t; cvta.to.shared.u64 t, %1; cvt.u32.u64 %0, t; }" : "=r"(a) : "l"(p));
  return a;
}

// ---------------------------------------------------------------------------
// Kernel 0: W2[k][n] -> bf16 hi/lo transposed to [n][k], via smem tile
// ---------------------------------------------------------------------------
__global__ void __launch_bounds__(256) prep_w2_kernel(const float* __restrict__ W2) {
  __shared__ float tile[64][72];
  int kb = blockIdx.x * 64, nb = blockIdx.y * 64;
  int tid = threadIdx.x;
#pragma unroll
  for (int i = 0; i < 4; i++) {
    int t2 = tid + i * 256;             // 1024 = 64 krows * 16 float4
    int r = t2 >> 4, q = t2 & 15;
    float4 v = *(const float4*)(W2 + (size_t)(kb + r) * DD + nb + q * 4);
    *(float4*)&tile[r][q * 4] = v;
  }
  __syncthreads();
#pragma unroll
  for (int i = 0; i < 2; i++) {
    int t2 = tid + i * 256;             // 512 = 64 nrows * 8 uint4
    int n = t2 >> 3, q = t2 & 7;
    uint32_t h[4], l[4];
#pragma unroll
    for (int e = 0; e < 4; e++) {
      float a = tile[q * 8 + e * 2 + 0][n];
      float b = tile[q * 8 + e * 2 + 1][n];
      split2(a, b, h[e], l[e]);
    }
    size_t off = (size_t)(nb + n) * DD + kb + q * 8;
    *(uint4*)(g_w2bf + off) = make_uint4(h[0], h[1], h[2], h[3]);
    *(uint4*)(g_w2bf + DD * DD + off) = make_uint4(l[0], l[1], l[2], l[3]);
  }
}

// ---------------------------------------------------------------------------
// Kernel 1: q_proj[b][n] = query[b]@W1 + b1 + b2
// ---------------------------------------------------------------------------
__global__ void __launch_bounds__(256) qproj_kernel(
    const float* __restrict__ query, const float* __restrict__ W1,
    const float* __restrict__ b1, const float* __restrict__ b2) {
  int b = blockIdx.x;
  __shared__ float qs[DD];
  for (int i = threadIdx.x; i < DD; i += 256) qs[i] = query[b * DD + i];
  __syncthreads();
  for (int n = threadIdx.x; n < DD; n += 256) {
    float acc = 0.f;
#pragma unroll 8
    for (int k = 0; k < DD; k++) acc = fmaf(qs[k], W1[k * DD + n], acc);
    g_qadd[b * DD + n] = acc + b1[n] + b2[n];
  }
}

// ---------------------------------------------------------------------------
// Kernel 2: score GEMM — ldmatrix + mma.sync bf16 3-term split, warp tile
// 32x32, block tile 64 rows x 128 cols per nc chunk, A resident, W2 cp.async.
// ---------------------------------------------------------------------------
#define A_STRIDE 1040          // (512+8) bf16 * 2 bytes; banks 4r mod 32
#define AHI_OFF 0
#define ALO_OFF 66560          // 64*1040
#define BST_OFF 133120
#define B_RSTRIDE 144          // (64+8) bf16 * 2 bytes
#define B_PLANE 18432          // 128 rows * 144
#define B_STAGE 36864          // hi + lo
#define Q_OFF 206848           // 133120 + 2*36864
#define V_OFF 208896
#define P_OFF 210944
#define SMEM_TOTAL 211968

__global__ void __launch_bounds__(256, 1) score_mma_kernel(
    const float* __restrict__ values, const float* __restrict__ Vv,
    const float* __restrict__ bv) {
  extern __shared__ char smem[];
  const uint32_t sb = smem_u32(smem);
  const int tid = threadIdx.x;
  const int wid = tid >> 5, lane = tid & 31;
  const int gid = lane >> 2, tig = lane & 3;
  const int wm = wid & 1, wn = wid >> 1;  // 2 m-warps x 4 n-warps
  const int m0 = blockIdx.x * 64;
  const int b = m0 >> 12;

  float* qsh = (float*)(smem + Q_OFF);
  float* vsh = (float*)(smem + V_OFF);
  float* part = (float*)(smem + P_OFF);

  // ---- A fill: 64 rows x 512 k -> bf16 hi/lo ----
  for (int task = tid; task < 4096; task += 256) {
    int r = task >> 6, g = task & 63;
    const float4* p4 = (const float4*)(values + (size_t)(m0 + r) * DD + g * 8);
    float4 x0 = p4[0], x1 = p4[1];
    uint32_t h0, h1, h2, h3, l0, l1, l2, l3;
    split2(x0.x, x0.y, h0, l0);
    split2(x0.z, x0.w, h1, l1);
    split2(x1.x, x1.y, h2, l2);
    split2(x1.z, x1.w, h3, l3);
    uint32_t off = (uint32_t)(r * A_STRIDE + g * 16);
    *(uint4*)(smem + AHI_OFF + off) = make_uint4(h0, h1, h2, h3);
    *(uint4*)(smem + ALO_OFF + off) = make_uint4(l0, l1, l2, l3);
  }
  for (int i = tid; i < DD; i += 256) {
    qsh[i] = g_qadd[b * DD + i];
    vsh[i] = Vv[i];
  }

  // ldmatrix per-lane addresses
  const int a_row = ((lane >> 3) & 1) * 8 + (lane & 7);
  const int a_col = (lane >> 4) * 16;
  const uint32_t aH_addr = sb + AHI_OFF + (wm * 32 + a_row) * A_STRIDE + a_col;
  const uint32_t aL_addr = aH_addr + (ALO_OFF - AHI_OFF);
  const int b_row = ((lane >> 4) & 1) * 8 + (lane & 7);
  const int b_col = ((lane >> 3) & 1) * 16;
  const uint32_t b_off = (wn * 32 + b_row) * B_RSTRIDE + b_col;

  // cp.async task mapping (per stage: 1024 rows-of-8k x hi/lo)
  float rowsum[4] = {0.f, 0.f, 0.f, 0.f};

  for (int nc = 0; nc < 4; ++nc) {
    float acc[2][4][4];
#pragma unroll
    for (int mi = 0; mi < 2; mi++)
#pragma unroll
      for (int ni = 0; ni < 4; ni++)
#pragma unroll
        for (int j = 0; j < 4; j++) acc[mi][ni][j] = 0.f;

    const unsigned short* Bg = g_w2bf + (size_t)(nc * 128) * DD;

    // issue stage 0 (kt=0)
    {
      uint32_t st = sb + BST_OFF;
#pragma unroll
      for (int i = 0; i < 4; i++) {
        int t2 = tid + i * 256;
        int r = t2 >> 3, q = t2 & 7;
        const unsigned short* src = Bg + (size_t)r * DD + q * 8;
        uint32_t dst = st + r * B_RSTRIDE + q * 16;
        cp16(dst, src);
        cp16(dst + B_PLANE, src + DD * DD);
      }
      CP_COMMIT();
    }

    for (int kt = 0; kt < 8; ++kt) {
      if (kt < 7) {
        uint32_t st = sb + BST_OFF + ((kt + 1) & 1) * B_STAGE;
        const unsigned short* Bk = Bg + (kt + 1) * 64;
#pragma unroll
        for (int i = 0; i < 4; i++) {
          int t2 = tid + i * 256;
          int r = t2 >> 3, q = t2 & 7;
          const unsigned short* src = Bk + (size_t)r * DD + q * 8;
          uint32_t dst = st + r * B_RSTRIDE + q * 16;
          cp16(dst, src);
          cp16(dst + B_PLANE, src + DD * DD);
        }
        CP_COMMIT();
        CP_WAIT1();
      } else {
        CP_WAIT0();
      }
      __syncthreads();  // stage kt ready (and A ready on first pass)

      const uint32_t stage = sb + BST_OFF + (kt & 1) * B_STAGE;
#pragma unroll
      for (int k16 = 0; k16 < 4; ++k16) {
        int kg = kt * 64 + k16 * 16;
        uint32_t aH[2][4], aL[2][4], bH[2][4], bL[2][4];
        ldsm_x4(aH[0], aH_addr + kg * 2);
        ldsm_x4(aH[1], aH_addr + 16 * A_STRIDE + kg * 2);
        ldsm_x4(aL[0], aL_addr + kg * 2);
        ldsm_x4(aL[1], aL_addr + 16 * A_STRIDE + kg * 2);
        uint32_t bbase = stage + b_off + k16 * 32;
        ldsm_x4(bH[0], bbase);
        ldsm_x4(bH[1], bbase + 16 * B_RSTRIDE);
        ldsm_x4(bL[0], bbase + B_PLANE);
        ldsm_x4(bL[1], bbase + B_PLANE + 16 * B_RSTRIDE);
#pragma unroll
        for (int mi = 0; mi < 2; mi++)
#pragma unroll
          for (int ni = 0; ni < 4; ni++) {
            const uint32_t* bh = &bH[ni >> 1][(ni & 1) * 2];
            const uint32_t* bl = &bL[ni >> 1][(ni & 1) * 2];
            mma_bf16(acc[mi][ni], aH[mi], bh);
            mma_bf16(acc[mi][ni], aH[mi], bl);
            mma_bf16(acc[mi][ni], aL[mi], bh);
          }
      }
      __syncthreads();  // all readers done before stage is overwritten
    }

    // epilogue for this 128-col chunk
#pragma unroll
    for (int mi = 0; mi < 2; mi++)
#pragma unroll
      for (int ni = 0; ni < 4; ni++)
#pragma unroll
        for (int j = 0; j < 4; j++) {
          int n = nc * 128 + wn * 32 + ni * 8 + tig * 2 + (j & 1);
          float h = tanh_fast(acc[mi][ni][j] + qsh[n]);
          rowsum[mi * 2 + (j >> 1)] = fmaf(h, vsh[n], rowsum[mi * 2 + (j >> 1)]);
        }
  }

#pragma unroll
  for (int i = 0; i < 4; i++) {
    rowsum[i] += __shfl_xor_sync(0xffffffffu, rowsum[i], 1);
    rowsum[i] += __shfl_xor_sync(0xffffffffu, rowsum[i], 2);
  }
  if (tig == 0) {
#pragma unroll
    for (int mi = 0; mi < 2; mi++)
#pragma unroll
      for (int ri = 0; ri < 2; ri++) {
        int row = wm * 32 + mi * 16 + ri * 8 + gid;
        part[wn * 64 + row] = rowsum[mi * 2 + ri];
      }
  }
  __syncthreads();
  if (tid < 64) {
    float s = part[tid] + part[64 + tid] + part[128 + tid] + part[192 + tid];
    g_scores[m0 + tid] = s + bv[0];
  }
}

// ---------------------------------------------------------------------------
// Kernel 3: softmax over S per batch, attn -> d_out[B*D ..]
// ---------------------------------------------------------------------------
__global__ void __launch_bounds__(256) softmax_kernel(float* __restrict__ out) {
  int b = blockIdx.x;
  const float* sc = g_scores + b * SS;
  float* attn = out + BB * DD + (size_t)b * SS;
  __shared__ float redm[8];
  __shared__ float reds[8];
  __shared__ float bm, bs;
  int tid = threadIdx.x, lane = tid & 31, w = tid >> 5;

  float m = -1e30f;
  for (int i = tid; i < SS; i += 256) m = fmaxf(m, sc[i]);
#pragma unroll
  for (int o = 16; o; o >>= 1) m = fmaxf(m, __shfl_xor_sync(0xffffffffu, m, o));
  if (lane == 0) redm[w] = m;
  __syncthreads();
  if (tid == 0) {
    float v = redm[0];
#pragma unroll
    for (int i = 1; i < 8; i++) v = fmaxf(v, redm[i]);
    bm = v;
  }
  __syncthreads();
  m = bm;

  float sum = 0.f;
  for (int i = tid; i < SS; i += 256) sum += expf(sc[i] - m);
#pragma unroll
  for (int o = 16; o; o >>= 1) sum += __shfl_xor_sync(0xffffffffu, sum, o);
  if (lane == 0) reds[w] = sum;
  __syncthreads();
  if (tid == 0) {
    float v = 0.f;
#pragma unroll
    for (int i = 0; i < 8; i++) v += reds[i];
    bs = v;
  }
  __syncthreads();
  float inv = 1.0f / bs;
  for (int i = tid; i < SS; i += 256) attn[i] = expf(sc[i] - m) * inv;
}

// ---------------------------------------------------------------------------
// Kernel 4/5: context = sum_s attn * values (deterministic two-stage)
// ---------------------------------------------------------------------------
__global__ void __launch_bounds__(128) ctx_partial_kernel(
    const float* __restrict__ values, const float* __restrict__ out) {
  int d = blockIdx.x * 128 + threadIdx.x;
  int scnk = blockIdx.y;
  int b = blockIdx.z;
  const float* attn = out + BB * DD + (size_t)b * SS + scnk * (SS / 8);
  const float* vb = values + ((size_t)b * SS + (size_t)scnk * (SS / 8)) * DD + d;
  float acc = 0.f;
  for (int s = 0; s < SS / 8; s += 8) {
#pragma unroll
    for (int u = 0; u < 8; u++)
      acc = fmaf(attn[s + u], vb[(size_t)(s + u) * DD], acc);
  }
  g_partial[((b * 8) + scnk) * DD + d] = acc;
}

__global__ void __launch_bounds__(256) ctx_reduce_kernel(float* __restrict__ out) {
  int idx = blockIdx.x * 256 + threadIdx.x;
  if (idx >= BB * DD) return;
  int b = idx >> 9;
  int d = idx & 511;
  float acc = 0.f;
#pragma unroll
  for (int p = 0; p < 8; p++) acc += g_partial[(b * 8 + p) * DD + d];
  out[idx] = acc;
}

// ---------------------------------------------------------------------------
extern "C" void kernel_launch(void* const* d_in, const int* in_sizes, int n_in,
                              void* d_out, int out_size) {
  const float* query = (const float*)d_in[0];
  const float* values = (const float*)d_in[1];
  const float* W1 = (const float*)d_in[2];
  const float* b1 = (const float*)d_in[3];
  const float* W2 = (const float*)d_in[4];
  const float* b2 = (const float*)d_in[5];
  const float* Vv = (const float*)d_in[6];
  const float* bv = (const float*)d_in[7];
  float* out = (float*)d_out;

  cudaFuncSetAttribute(score_mma_kernel,
                       cudaFuncAttributeMaxDynamicSharedMemorySize, SMEM_TOTAL);

  prep_w2_kernel<<<dim3(8, 8), 256>>>(W2);
  qproj_kernel<<<BB, 256>>>(query, W1, b1, b2);
  score_mma_kernel<<<(BB * SS) / 64, 256, SMEM_TOTAL>>>(values, Vv, bv);
  softmax_kernel<<<BB, 256>>>(out);
  ctx_partial_kernel<<<dim3(DD / 128, 8, BB), 128>>>(values, out);
  ctx_reduce_kernel<<<(BB * DD + 255) / 256, 256>>>(out);
}